// round 16
// baseline (speedup 1.0000x reference)
#include <cuda_runtime.h>
#include <cuda_fp16.h>
#include <cstdint>

#define CIN   32
#define COUT  64
#define TT    8
#define DDIM  32
#define HDIM  64
#define WDIM  64

// xs2: [row(18 = 3d x 6h)][wc(68)][cp(16)] half2 words, 16B quarters XOR-swizzled:
//   word(row,wc,cp) = (row*68 + wc)*16 + (q ^ ((wc>>1)&3))*4 + (cp&3),  q = cp>>2
#define NPOS      (18 * 68)            // 1224 positions
#define XS2_SIZE  (NPOS * 16)          // 19584 words
#define SMEM_BYTES (XS2_SIZE * 4)      // 78336 B -> 2 blocks/SM

// fused weights, fp16 frag layout: g_w2[((b*2+cg)*27+s)*32+lane][16 u32]
__device__ uint32_t g_w2[4 * 2 * 27 * 32 * 16];   // 442 KB

// prepacked x: [b][d][h][w][cp16] half2 words (16.8M words = 33.5 MB)
#define XPLANE (DDIM * HDIM * WDIM)    // 131072 positions per batch
__device__ uint32_t g_xh[4 * XPLANE * 16];

__device__ __forceinline__ uint32_t smem_u32(const void* p) {
    uint32_t a;
    asm("{ .reg .u64 t; cvta.to.shared.u64 t, %1; cvt.u32.u64 %0, t; }" : "=r"(a) : "l"(p));
    return a;
}
__device__ __forceinline__ void ldsm_x4(uint32_t* r, uint32_t a) {
    asm volatile("ldmatrix.sync.aligned.m8n8.x4.shared.b16 {%0,%1,%2,%3}, [%4];"
                 : "=r"(r[0]), "=r"(r[1]), "=r"(r[2]), "=r"(r[3]) : "r"(a));
}
__device__ __forceinline__ void sts128(uint32_t a, uint4 v) {
    asm volatile("st.shared.v4.b32 [%0], {%1,%2,%3,%4};"
                 :: "r"(a), "r"(v.x), "r"(v.y), "r"(v.z), "r"(v.w));
}
__device__ __forceinline__ void mma_f16(float* c,
                                        uint32_t a0, uint32_t a1, uint32_t a2, uint32_t a3,
                                        uint32_t b0, uint32_t b1) {
    asm volatile("mma.sync.aligned.m16n8k16.row.col.f32.f16.f16.f32 "
                 "{%0,%1,%2,%3}, {%4,%5,%6,%7}, {%8,%9}, {%0,%1,%2,%3};"
                 : "+f"(c[0]), "+f"(c[1]), "+f"(c[2]), "+f"(c[3])
                 : "r"(a0), "r"(a1), "r"(a2), "r"(a3), "r"(b0), "r"(b1));
}

// ---------- init 1: w'[b,o,c,s] = sum_t weight[o,c,t]*stencils[b,t,s] -> fp16 frags ----------
__global__ void init_w2_kernel(const float* __restrict__ weight,
                               const float* __restrict__ stencils) {
    int idx  = blockIdx.x * 256 + threadIdx.x;   // 0 .. 110591
    int r    = idx & 15;
    int lane = (idx >> 4) & 31;
    int s    = (idx >> 9) % 27;
    int rest = (idx >> 9) / 27;                  // b*2 + cg
    int cg = rest & 1, b = rest >> 1;
    int nf = r >> 1, half = r & 1;
    int o  = nf * 8 + (lane >> 2);
    int cA = cg * 16 + half * 8 + 2 * (lane & 3);
    float va = 0.f, vb = 0.f;
    #pragma unroll
    for (int t = 0; t < TT; t++) {
        float st = stencils[(b * TT + t) * 27 + s];
        va += weight[(o * CIN + cA) * TT + t] * st;
        vb += weight[(o * CIN + cA + 1) * TT + t] * st;
    }
    __half2 h = __floats2half2_rn(va, vb);
    g_w2[idx] = *reinterpret_cast<uint32_t*>(&h);
}

// ---------- init 2: prepack x -> [b][pos][cp16] half2 ----------
__global__ void init_xh_kernel(const float* __restrict__ x) {
    int pos_all = blockIdx.x * 256 + threadIdx.x;   // 0 .. 524287 (b*XPLANE + sp)
    int cp = blockIdx.y;                            // 0..15
    int b  = pos_all >> 17;                         // /XPLANE
    int sp = pos_all & (XPLANE - 1);
    const float* p0 = x + ((size_t)(b * CIN + 2 * cp)) * XPLANE + sp;
    __half2 h = __floats2half2_rn(p0[0], p0[XPLANE]);
    g_xh[(size_t)pos_all * 16 + cp] = *reinterpret_cast<uint32_t*>(&h);
}

__global__ __launch_bounds__(256, 2)
void stencilconv3d_kernel(const float* __restrict__ bias,
                          float* __restrict__ out) {
    extern __shared__ uint32_t sm[];
    const uint32_t smb = smem_u32(sm);

    const int h0  = blockIdx.x;   // 0..15 (4 output h rows)
    const int d0  = blockIdx.y;   // 0..31
    const int bz  = blockIdx.z;   // 0..3
    const int tid = threadIdx.x;
    const int wid = tid >> 5;     // 0..7
    const int lane = tid & 31;

    // warp mapping: hl = h row (0..3), oh = o half (0..1)
    const int hl = wid >> 1;
    const int oh = wid & 1;

    const int hbase = h0 * 4 - 1;

    // ---- load x tile from prepacked g_xh: 4x LDG.128 + 4x swizzled STS.128 / pos ----
    {
        const uint4* xq = (const uint4*)g_xh + (size_t)bz * XPLANE * 4;
        for (int p = tid; p < NPOS; p += 256) {
            int row = p / 68, wc = p - row * 68;
            int dz = row / 6,  hq = row - dz * 6;
            int dg = d0 + dz - 1;
            int hg = hbase + hq;
            int wg = wc - 1;
            uint4 v[4];
            if (wc < 66 && (unsigned)dg < DDIM && (unsigned)hg < HDIM && (unsigned)wg < WDIM) {
                const uint4* pp = xq + (size_t)(((dg * HDIM) + hg) * WDIM + wg) * 4;
                v[0] = __ldg(pp + 0); v[1] = __ldg(pp + 1);
                v[2] = __ldg(pp + 2); v[3] = __ldg(pp + 3);
            } else {
                v[0] = v[1] = v[2] = v[3] = make_uint4(0u, 0u, 0u, 0u);
            }
            const int fsw = (wc >> 1) & 3;
            uint32_t base = smb + (uint32_t)(p * 16) * 4u;
            #pragma unroll
            for (int q = 0; q < 4; q++)
                sts128(base + (uint32_t)((q ^ fsw) * 4) * 4u, v[q]);
        }
    }
    __syncthreads();   // the ONLY block barrier

    float acc[4][4][4];           // [m-frag(16 w each)][n-frag(8 o, this half)][c]
    #pragma unroll
    for (int i = 0; i < 4; i++)
        #pragma unroll
        for (int j = 0; j < 4; j++)
            #pragma unroll
            for (int c = 0; c < 4; c++) acc[i][j][c] = 0.f;

    // per-lane ldmatrix geometry
    const int wbase = ((lane >> 3) & 1) * 8 + (lane & 7);  // w within 16-w m-tile
    const int qsel  = lane >> 4;                           // 0 = k0-7, 1 = k8-15

    // ---- GEMM: 54 flattened k16-steps, A double-buffered ----
    const uint4* wp = (const uint4*)g_w2
                    + ((size_t)(bz * 2) * 27 * 32 + lane) * 4 + oh * 2;

    uint32_t afA[4][4], afB[4][4];

    // A-frag address for flattened step ss
    #define LD_A(ss, af) do {                                                   \
        const int cg_ = (ss) / 27;                                              \
        const int s_  = (ss) - cg_ * 27;                                        \
        const int srow_ = (s_ / 9) * 6 + ((s_ % 9) / 3) + hl;                   \
        const int wcL_  = wbase + s_ % 3;                                       \
        const int qp_   = (qsel + cg_ * 2) ^ ((wcL_ >> 1) & 3);                 \
        uint32_t a_ = smb + (uint32_t)(((srow_ * 68 + wcL_) * 16) + qp_ * 4) * 4u; \
        ldsm_x4((af)[0], a_);                                                   \
        ldsm_x4((af)[1], a_ + 1024u);                                           \
        ldsm_x4((af)[2], a_ + 2048u);                                           \
        ldsm_x4((af)[3], a_ + 3072u);                                           \
    } while (0)

    LD_A(0, afA);
    #pragma unroll
    for (int ss = 0; ss < 54; ss++) {
        uint32_t (*cur)[4] = (ss & 1) ? afB : afA;
        uint32_t (*nxt)[4] = (ss & 1) ? afA : afB;
        if (ss + 1 < 54) LD_A(ss + 1, nxt);
        const uint4* wps = wp + (size_t)ss * 128;
        uint4 q0 = __ldg(wps + 0);      // nf_local 0,1
        uint4 q1 = __ldg(wps + 1);      // nf_local 2,3
        #pragma unroll
        for (int mf = 0; mf < 4; mf++) {
            mma_f16(acc[mf][0], cur[mf][0], cur[mf][1], cur[mf][2], cur[mf][3], q0.x, q0.y);
            mma_f16(acc[mf][1], cur[mf][0], cur[mf][1], cur[mf][2], cur[mf][3], q0.z, q0.w);
            mma_f16(acc[mf][2], cur[mf][0], cur[mf][1], cur[mf][2], cur[mf][3], q1.x, q1.y);
            mma_f16(acc[mf][3], cur[mf][0], cur[mf][1], cur[mf][2], cur[mf][3], q1.z, q1.w);
        }
    }
    #undef LD_A

    // ---- epilogue: registers -> gmem, + bias ----
    {
        const size_t ostride = (size_t)DDIM * HDIM * WDIM;
        const int h = h0 * 4 + hl;
        const size_t obase = (size_t)bz * COUT * ostride
                           + (size_t)d0 * HDIM * WDIM + (size_t)h * WDIM;
        #pragma unroll
        for (int nf = 0; nf < 4; nf++) {
            int o0 = oh * 32 + nf * 8 + (lane & 3) * 2;
            float bv0 = __ldg(&bias[o0]);
            float bv1 = __ldg(&bias[o0 + 1]);
            #pragma unroll
            for (int mf = 0; mf < 4; mf++) {
                #pragma unroll
                for (int cc = 0; cc < 4; cc++) {
                    float sv = acc[mf][nf][cc];
                    int o = o0 + (cc & 1);
                    int w = mf * 16 + (lane >> 2) + ((cc >> 1) & 1) * 8;
                    out[obase + (size_t)o * ostride + w]
                        = sv + ((cc & 1) ? bv1 : bv0);
                }
            }
        }
    }
}

extern "C" void kernel_launch(void* const* d_in, const int* in_sizes, int n_in,
                              void* d_out, int out_size) {
    const float* x        = (const float*)d_in[0];
    const float* stencils = (const float*)d_in[1];
    const float* weight   = (const float*)d_in[2];
    const float* bias     = (const float*)d_in[3];
    float* out = (float*)d_out;

    init_w2_kernel<<<432, 256>>>(weight, stencils);
    {
        dim3 g(4 * XPLANE / 256, 16);
        init_xh_kernel<<<g, 256>>>(x);
    }

    cudaFuncSetAttribute(stencilconv3d_kernel,
                         cudaFuncAttributeMaxDynamicSharedMemorySize, SMEM_BYTES);
    dim3 grid(HDIM / 4, DDIM, 4);   // 16 x 32 x 4 = 2048 blocks
    stencilconv3d_kernel<<<grid, 256, SMEM_BYTES>>>(bias, out);
}

// round 17
// speedup vs baseline: 1.2343x; 1.2343x over previous
#include <cuda_runtime.h>
#include <cuda_fp16.h>
#include <cstdint>

#define CIN   32
#define COUT  64
#define TT    8
#define DDIM  32
#define HDIM  64
#define WDIM  64

// xs2: [row(18 = 3d x 6h)][wc(68)][cp(16)] half2 words, 16B quarters XOR-swizzled:
//   word(row,wc,cp) = (row*68 + wc)*16 + (q ^ ((wc>>1)&3))*4 + (cp&3),  q = cp>>2
#define NPOS      (18 * 68)            // 1224 positions
#define XS2_SIZE  (NPOS * 16)          // 19584 words
#define SMEM_BYTES (XS2_SIZE * 4)      // 78336 B -> 2 blocks/SM

// fused weights, fp16 frag layout: g_w2[((b*2+cg)*27+s)*32+lane][16 u32]
__device__ uint32_t g_w2[4 * 2 * 27 * 32 * 16];   // 110592 u32

__device__ __forceinline__ uint32_t smem_u32(const void* p) {
    uint32_t a;
    asm("{ .reg .u64 t; cvta.to.shared.u64 t, %1; cvt.u32.u64 %0, t; }" : "=r"(a) : "l"(p));
    return a;
}
__device__ __forceinline__ void ldsm_x4(uint32_t* r, uint32_t a) {
    asm volatile("ldmatrix.sync.aligned.m8n8.x4.shared.b16 {%0,%1,%2,%3}, [%4];"
                 : "=r"(r[0]), "=r"(r[1]), "=r"(r[2]), "=r"(r[3]) : "r"(a));
}
__device__ __forceinline__ void sts128(uint32_t a, uint32_t v0, uint32_t v1,
                                       uint32_t v2, uint32_t v3) {
    asm volatile("st.shared.v4.b32 [%0], {%1,%2,%3,%4};"
                 :: "r"(a), "r"(v0), "r"(v1), "r"(v2), "r"(v3));
}
__device__ __forceinline__ void mma_f16(float* c,
                                        uint32_t a0, uint32_t a1, uint32_t a2, uint32_t a3,
                                        uint32_t b0, uint32_t b1) {
    asm volatile("mma.sync.aligned.m16n8k16.row.col.f32.f16.f16.f32 "
                 "{%0,%1,%2,%3}, {%4,%5,%6,%7}, {%8,%9}, {%0,%1,%2,%3};"
                 : "+f"(c[0]), "+f"(c[1]), "+f"(c[2]), "+f"(c[3])
                 : "r"(a0), "r"(a1), "r"(a2), "r"(a3), "r"(b0), "r"(b1));
}

// ---------- init: w'[b,o,c,s] = sum_t weight[o,c,t]*stencils[b,t,s] -> fp16 frags ----------
__global__ void init_w2_kernel(const float* __restrict__ weight,
                               const float* __restrict__ stencils) {
    int idx  = blockIdx.x * 256 + threadIdx.x;   // 0 .. 110591
    int r    = idx & 15;
    int lane = (idx >> 4) & 31;
    int s    = (idx >> 9) % 27;
    int rest = (idx >> 9) / 27;                  // b*2 + cg
    int cg = rest & 1, b = rest >> 1;
    int nf = r >> 1, half = r & 1;
    int o  = nf * 8 + (lane >> 2);
    int cA = cg * 16 + half * 8 + 2 * (lane & 3);
    float va = 0.f, vb = 0.f;
    #pragma unroll
    for (int t = 0; t < TT; t++) {
        float st = stencils[(b * TT + t) * 27 + s];
        va += weight[(o * CIN + cA) * TT + t] * st;
        vb += weight[(o * CIN + cA + 1) * TT + t] * st;
    }
    __half2 h = __floats2half2_rn(va, vb);
    g_w2[idx] = *reinterpret_cast<uint32_t*>(&h);
}

__global__ __launch_bounds__(256, 2)
void stencilconv3d_kernel(const float* __restrict__ x,
                          const float* __restrict__ bias,
                          float* __restrict__ out) {
    extern __shared__ uint32_t sm[];
    const uint32_t smb = smem_u32(sm);

    const int h0  = blockIdx.x;   // 0..15 (4 output h rows)
    const int d0  = blockIdx.y;   // 0..31
    const int bz  = blockIdx.z;   // 0..3
    const int tid = threadIdx.x;
    const int wid = tid >> 5;     // 0..7
    const int lane = tid & 31;

    // warp mapping: hl = h row (0..3), oh = o half (0..1)
    const int hl = wid >> 1;
    const int oh = wid & 1;

    const size_t x_plane = (size_t)DDIM * HDIM * WDIM;
    const int hbase = h0 * 4 - 1;

    // ---- load x tile: per position, 32 channels -> 16 half2, swizzled quarters ----
    {
        const float* xc = x + (size_t)bz * CIN * x_plane;
        for (int p = tid; p < NPOS; p += 256) {
            int row = p / 68, wc = p - row * 68;
            int dz = row / 6,  hq = row - dz * 6;
            int dg = d0 + dz - 1;
            int hg = hbase + hq;
            int wg = wc - 1;
            uint32_t hw[16];
            if (wc < 66 && (unsigned)dg < DDIM && (unsigned)hg < HDIM && (unsigned)wg < WDIM) {
                const float* pp = xc + ((size_t)dg * HDIM + hg) * WDIM + wg;
                #pragma unroll
                for (int j = 0; j < 16; j++) {
                    float v0 = pp[(size_t)(2 * j) * x_plane];
                    float v1 = pp[(size_t)(2 * j + 1) * x_plane];
                    __half2 h = __floats2half2_rn(v0, v1);
                    hw[j] = *reinterpret_cast<uint32_t*>(&h);
                }
            } else {
                #pragma unroll
                for (int j = 0; j < 16; j++) hw[j] = 0u;
            }
            const int fsw = (wc >> 1) & 3;
            uint32_t base = smb + (uint32_t)(p * 16) * 4u;
            #pragma unroll
            for (int q = 0; q < 4; q++) {
                uint32_t a = base + (uint32_t)((q ^ fsw) * 4) * 4u;
                sts128(a, hw[q * 4 + 0], hw[q * 4 + 1], hw[q * 4 + 2], hw[q * 4 + 3]);
            }
        }
    }
    __syncthreads();   // the ONLY block barrier

    float acc[4][4][4];           // [m-frag(16 w each)][n-frag(8 o, this half)][c]
    #pragma unroll
    for (int i = 0; i < 4; i++)
        #pragma unroll
        for (int j = 0; j < 4; j++)
            #pragma unroll
            for (int c = 0; c < 4; c++) acc[i][j][c] = 0.f;

    // per-lane ldmatrix geometry
    const int wbase = ((lane >> 3) & 1) * 8 + (lane & 7);  // w within 16-w m-tile
    const int qsel  = lane >> 4;                           // 0 = k0-7, 1 = k8-15

    // ---- GEMM: 54 flattened k16-steps (2 cg x 27 s), A double-buffered ----
    const uint4* wp = (const uint4*)g_w2
                    + ((size_t)(bz * 2) * 27 * 32 + lane) * 4 + oh * 2;

    uint32_t afA[4][4], afB[4][4];

    #define LD_A(ss, af) do {                                                      \
        const int cg_ = (ss) / 27;                                                 \
        const int s_  = (ss) - cg_ * 27;                                           \
        const int srow_ = (s_ / 9) * 6 + ((s_ % 9) / 3) + hl;                      \
        const int wcL_  = wbase + s_ % 3;                                          \
        const int qp_   = (qsel + cg_ * 2) ^ ((wcL_ >> 1) & 3);                    \
        uint32_t a_ = smb + (uint32_t)(((srow_ * 68 + wcL_) * 16) + qp_ * 4) * 4u; \
        ldsm_x4((af)[0], a_);                                                      \
        ldsm_x4((af)[1], a_ + 1024u);                                              \
        ldsm_x4((af)[2], a_ + 2048u);                                              \
        ldsm_x4((af)[3], a_ + 3072u);                                              \
    } while (0)

    LD_A(0, afA);
    #pragma unroll
    for (int ss = 0; ss < 54; ss++) {
        uint32_t (*cur)[4] = (ss & 1) ? afB : afA;
        uint32_t (*nxt)[4] = (ss & 1) ? afA : afB;
        if (ss + 1 < 54) LD_A(ss + 1, nxt);
        const uint4* wps = wp + (size_t)ss * 128;
        uint4 q0 = __ldg(wps + 0);      // nf_local 0,1
        uint4 q1 = __ldg(wps + 1);      // nf_local 2,3
        #pragma unroll
        for (int mf = 0; mf < 4; mf++) {
            mma_f16(acc[mf][0], cur[mf][0], cur[mf][1], cur[mf][2], cur[mf][3], q0.x, q0.y);
            mma_f16(acc[mf][1], cur[mf][0], cur[mf][1], cur[mf][2], cur[mf][3], q0.z, q0.w);
            mma_f16(acc[mf][2], cur[mf][0], cur[mf][1], cur[mf][2], cur[mf][3], q1.x, q1.y);
            mma_f16(acc[mf][3], cur[mf][0], cur[mf][1], cur[mf][2], cur[mf][3], q1.z, q1.w);
        }
    }
    #undef LD_A

    // ---- epilogue: registers -> gmem, + bias ----
    {
        const size_t ostride = (size_t)DDIM * HDIM * WDIM;
        const int h = h0 * 4 + hl;
        const size_t obase = (size_t)bz * COUT * ostride
                           + (size_t)d0 * HDIM * WDIM + (size_t)h * WDIM;
        #pragma unroll
        for (int nf = 0; nf < 4; nf++) {
            int o0 = oh * 32 + nf * 8 + (lane & 3) * 2;
            float bv0 = __ldg(&bias[o0]);
            float bv1 = __ldg(&bias[o0 + 1]);
            #pragma unroll
            for (int mf = 0; mf < 4; mf++) {
                #pragma unroll
                for (int cc = 0; cc < 4; cc++) {
                    float sv = acc[mf][nf][cc];
                    int o = o0 + (cc & 1);
                    int w = mf * 16 + (lane >> 2) + ((cc >> 1) & 1) * 8;
                    out[obase + (size_t)o * ostride + w]
                        = sv + ((cc & 1) ? bv1 : bv0);
                }
            }
        }
    }
}

extern "C" void kernel_launch(void* const* d_in, const int* in_sizes, int n_in,
                              void* d_out, int out_size) {
    const float* x        = (const float*)d_in[0];
    const float* stencils = (const float*)d_in[1];
    const float* weight   = (const float*)d_in[2];
    const float* bias     = (const float*)d_in[3];
    float* out = (float*)d_out;

    init_w2_kernel<<<432, 256>>>(weight, stencils);

    cudaFuncSetAttribute(stencilconv3d_kernel,
                         cudaFuncAttributeMaxDynamicSharedMemorySize, SMEM_BYTES);
    dim3 grid(HDIM / 4, DDIM, 4);   // 16 x 32 x 4 = 2048 blocks
    stencilconv3d_kernel<<<grid, 256, SMEM_BYTES>>>(x, bias, out);
}